// round 6
// baseline (speedup 1.0000x reference)
#include <cuda_runtime.h>

// MotionProjector: out[b,c,v] = sum_{k<7} mask[b,k,v] * (A_bk · g(v) + bvec_bk)_c
// where A = R - I, bvec = (I - R) pivot + trans, pivot = weighted centroid of mask over grid.
// grids == meshgrid(linspace(-1,1,64)^3) computed analytically from voxel index.

namespace {
constexpr int Sd   = 64;
constexpr int VOX  = Sd * Sd * Sd;   // 262144
constexpr int V4   = VOX / 4;        // 65536 float4 per (b,k) slice
constexpr int Bn   = 4;
constexpr int KM   = 7;              // moving parts (k = K-1 contributes zero)
constexpr int NBK  = Bn * KM;        // 28
constexpr int CH   = 64;             // partial chunks per (b,k) in pass 1
}

__device__ float4 g_partials[NBK * CH];
__device__ float  g_coeffs[NBK * 12];   // per (b,k): A row-major [0..8], bvec [9..11]

__device__ __forceinline__ float coordf(int idx) {
    return fmaf((float)idx, 2.0f / 63.0f, -1.0f);
}

// ---------------------------------------------------------------------------
// Pass 1: per-(b,k) partial sums of (m, m*gx, m*gy, m*gz) over voxel chunks.
// grid = (CH, NBK), block = 256.  Each block reduces 4096 voxels (1024 float4).
// ---------------------------------------------------------------------------
__global__ __launch_bounds__(256) void reduce_kernel(const float* __restrict__ mask) {
    const int bk = blockIdx.y;
    const int b  = bk / KM;
    const int k  = bk % KM;
    const float4* __restrict__ m =
        reinterpret_cast<const float4*>(mask) + (size_t)(b * 8 + k) * V4;
    const int t = threadIdx.x;

    float s = 0.f, sx = 0.f, sy = 0.f, sz = 0.f;
    const int base = blockIdx.x * 1024;
#pragma unroll
    for (int r = 0; r < 4; ++r) {
        const int q = base + r * 256 + t;   // float4 index
        const int v = q << 2;               // voxel index
        const float4 mv = m[q];
        const float gx = coordf(v >> 12);
        const float gy = coordf((v >> 6) & 63);
        const int   l  = v & 63;
        const float ms = (mv.x + mv.y) + (mv.z + mv.w);
        s  += ms;
        sx  = fmaf(ms, gx, sx);
        sy  = fmaf(ms, gy, sy);
        sz += mv.x * coordf(l)     + mv.y * coordf(l + 1)
            + mv.z * coordf(l + 2) + mv.w * coordf(l + 3);
    }

    // warp reduce
#pragma unroll
    for (int o = 16; o > 0; o >>= 1) {
        s  += __shfl_down_sync(0xffffffffu, s,  o);
        sx += __shfl_down_sync(0xffffffffu, sx, o);
        sy += __shfl_down_sync(0xffffffffu, sy, o);
        sz += __shfl_down_sync(0xffffffffu, sz, o);
    }
    __shared__ float4 red[8];
    const int w = t >> 5, lane = t & 31;
    if (lane == 0) red[w] = make_float4(s, sx, sy, sz);
    __syncthreads();
    if (w == 0) {
        float4 v4 = (lane < 8) ? red[lane] : make_float4(0.f, 0.f, 0.f, 0.f);
        s = v4.x; sx = v4.y; sy = v4.z; sz = v4.w;
#pragma unroll
        for (int o = 4; o > 0; o >>= 1) {
            s  += __shfl_down_sync(0xffffffffu, s,  o);
            sx += __shfl_down_sync(0xffffffffu, sx, o);
            sy += __shfl_down_sync(0xffffffffu, sy, o);
            sz += __shfl_down_sync(0xffffffffu, sz, o);
        }
        if (lane == 0) g_partials[bk * CH + blockIdx.x] = make_float4(s, sx, sy, sz);
    }
}

// ---------------------------------------------------------------------------
// Pass 2: fold partials -> pivot; build affine coeffs A = R - I, bvec = t + p - R p.
// 1 block, 32 threads (28 active). Fixed-order sums => deterministic.
// ---------------------------------------------------------------------------
__global__ __launch_bounds__(32) void coeff_kernel(const float* __restrict__ trans,
                                                   const float* __restrict__ rot) {
    const int tid = threadIdx.x;
    if (tid >= NBK) return;
    const int b = tid / KM, k = tid % KM;

    float s = 0.f, sx = 0.f, sy = 0.f, sz = 0.f;
    for (int c = 0; c < CH; ++c) {
        const float4 p = g_partials[tid * CH + c];
        s += p.x; sx += p.y; sy += p.z; sz += p.w;
    }
    const float px = sx / s, py = sy / s, pz = sz / s;

    const float* __restrict__ R = rot   + (size_t)(b * KM + k) * 9;
    const float* __restrict__ T = trans + (size_t)(b * KM + k) * 3;
    float* __restrict__ C = g_coeffs + tid * 12;
    const float pv[3] = {px, py, pz};
#pragma unroll
    for (int r = 0; r < 3; ++r) {
        const float r0 = R[r * 3 + 0], r1 = R[r * 3 + 1], r2 = R[r * 3 + 2];
        C[r * 3 + 0] = r0 - (r == 0 ? 1.f : 0.f);
        C[r * 3 + 1] = r1 - (r == 1 ? 1.f : 0.f);
        C[r * 3 + 2] = r2 - (r == 2 ? 1.f : 0.f);
        C[9 + r]     = T[r] + pv[r] - (r0 * px + r1 * py + r2 * pz);
    }
}

// ---------------------------------------------------------------------------
// Pass 3: out[b,c,v] = sum_k mask[b,k,v] * (A_k g + b_k)_c.  float4 per thread.
// grid = (V4/256, Bn), block = 256.
// ---------------------------------------------------------------------------
__global__ __launch_bounds__(256) void motion_kernel(const float* __restrict__ mask,
                                                     float* __restrict__ out) {
    const int b = blockIdx.y;
    __shared__ float sc[KM * 12];
    const int t = threadIdx.x;
    if (t < KM * 12) sc[t] = g_coeffs[b * KM * 12 + t];
    __syncthreads();

    const int q = blockIdx.x * 256 + t;      // float4 index in [0, V4)
    const int v = q << 2;
    const float gx  = coordf(v >> 12);
    const float gy  = coordf((v >> 6) & 63);
    const int   l   = v & 63;
    const float gz0 = coordf(l),     gz1 = coordf(l + 1);
    const float gz2 = coordf(l + 2), gz3 = coordf(l + 3);

    float4 acc0 = make_float4(0.f, 0.f, 0.f, 0.f);
    float4 acc1 = make_float4(0.f, 0.f, 0.f, 0.f);
    float4 acc2 = make_float4(0.f, 0.f, 0.f, 0.f);

    const float4* __restrict__ mb =
        reinterpret_cast<const float4*>(mask) + (size_t)b * 8 * V4;

#pragma unroll
    for (int k = 0; k < KM; ++k) {
        const float4 m = mb[(size_t)k * V4 + q];
        const float* __restrict__ C = sc + k * 12;

        // c = 0
        {
            const float com = fmaf(C[0], gx, fmaf(C[1], gy, C[9]));
            const float a2  = C[2];
            acc0.x = fmaf(m.x, fmaf(a2, gz0, com), acc0.x);
            acc0.y = fmaf(m.y, fmaf(a2, gz1, com), acc0.y);
            acc0.z = fmaf(m.z, fmaf(a2, gz2, com), acc0.z);
            acc0.w = fmaf(m.w, fmaf(a2, gz3, com), acc0.w);
        }
        // c = 1
        {
            const float com = fmaf(C[3], gx, fmaf(C[4], gy, C[10]));
            const float a2  = C[5];
            acc1.x = fmaf(m.x, fmaf(a2, gz0, com), acc1.x);
            acc1.y = fmaf(m.y, fmaf(a2, gz1, com), acc1.y);
            acc1.z = fmaf(m.z, fmaf(a2, gz2, com), acc1.z);
            acc1.w = fmaf(m.w, fmaf(a2, gz3, com), acc1.w);
        }
        // c = 2
        {
            const float com = fmaf(C[6], gx, fmaf(C[7], gy, C[11]));
            const float a2  = C[8];
            acc2.x = fmaf(m.x, fmaf(a2, gz0, com), acc2.x);
            acc2.y = fmaf(m.y, fmaf(a2, gz1, com), acc2.y);
            acc2.z = fmaf(m.z, fmaf(a2, gz2, com), acc2.z);
            acc2.w = fmaf(m.w, fmaf(a2, gz3, com), acc2.w);
        }
    }

    float4* __restrict__ ob = reinterpret_cast<float4*>(out);
    ob[(size_t)(b * 3 + 0) * V4 + q] = acc0;
    ob[(size_t)(b * 3 + 1) * V4 + q] = acc1;
    ob[(size_t)(b * 3 + 2) * V4 + q] = acc2;
}

// ---------------------------------------------------------------------------
extern "C" void kernel_launch(void* const* d_in, const int* in_sizes, int n_in,
                              void* d_out, int out_size) {
    const float* mask  = (const float*)d_in[0];   // (4, 8, 64, 64, 64)
    const float* trans = (const float*)d_in[1];   // (4, 7, 3)
    const float* rot   = (const float*)d_in[2];   // (4, 7, 3, 3)
    // d_in[3] = grids — recomputed analytically, not read.
    float* out = (float*)d_out;                   // (4, 3, 64, 64, 64)

    reduce_kernel<<<dim3(CH, NBK), 256>>>(mask);
    coeff_kernel<<<1, 32>>>(trans, rot);
    motion_kernel<<<dim3(V4 / 256, Bn), 256>>>(mask, out);
}